// round 8
// baseline (speedup 1.0000x reference)
#include <cuda_runtime.h>
#include <cstdint>

#define HH 128
#define WW 128
#define HWSZ (128*128)
#define BB 32
#define CC 16
#define NT 15   /* C-1 recurrent steps */

// ---------------- device scratch (no allocations allowed) ----------------
__device__ __align__(16) float  g_zi[(size_t)NT * BB * HWSZ]; // 31.5 MB zi
__device__ float2 g_h[2][(size_t)BB * HWSZ];        // double-buffered hidden (f0,f1)
__device__ float2 g_c[2][(size_t)BB * HWSZ];        // double-buffered cell
__device__ float  g_part[BB * 16];                  // per (batch, tile) lp partials

// ---------------- fast math helpers ----------------
__device__ __forceinline__ float ftanh(float x) {
    float y;
    asm("tanh.approx.f32 %0, %1;" : "=f"(y) : "f"(x));
    return y;
}
__device__ __forceinline__ float fsig(float x) {
    return fmaf(0.5f, ftanh(0.5f * x), 0.5f);
}
// packed f32x2 (Blackwell): d = a*b + d, both lanes; IEEE rn => bit-identical
__device__ __forceinline__ uint64_t pk2(float lo, float hi) {
    uint64_t r;
    asm("mov.b64 %0, {%1, %2};" : "=l"(r) : "f"(lo), "f"(hi));
    return r;
}
__device__ __forceinline__ void upk2(uint64_t v, float& lo, float& hi) {
    asm("mov.b64 {%0, %1}, %2;" : "=f"(lo), "=f"(hi) : "l"(v));
}
__device__ __forceinline__ void ffma2(uint64_t& d, uint64_t a, uint64_t b) {
    asm("fma.rn.f32x2 %0, %1, %2, %0;" : "+l"(d) : "l"(a), "l"(b));
}

// ---------------- kernels ----------------
// zi precompute: 4 outputs per thread along j; also zeroes h/c/part state.
__global__ void k_zi(const float* __restrict__ x, const float* __restrict__ Win,
                     const float* __restrict__ b_in) {
    int gid = blockIdx.x * 256 + threadIdx.x;
    if (gid >= NT * BB * 128 * 32) return;

    if (gid < BB * HWSZ) {
        g_h[0][gid] = make_float2(0.f, 0.f);
        g_c[0][gid] = make_float2(0.f, 0.f);
        if (gid < BB * 16) g_part[gid] = 0.f;
    }

    int j0 = (gid & 31) * 4;
    int i  = (gid >> 5) & 127;
    int n  = gid >> 12;          // n = t*32 + b  (matches reference reshape order)
    int t = n >> 5, b = n & 31;
    const float* xb = x + (size_t)(b * CC + t) * HWSZ;
    float w[9];
    #pragma unroll
    for (int k = 0; k < 9; k++) w[k] = __ldg(Win + k);
    const float bi = __ldg(b_in);
    float acc[4] = {bi, bi, bi, bi};
    #pragma unroll
    for (int kh = 0; kh < 3; kh++) {
        int ii = i + kh - 1;
        if ((unsigned)ii >= 128u) continue;
        const float* row = xb + ii * WW;
        float v[6];
        #pragma unroll
        for (int q = 0; q < 6; q++) {
            int jj = j0 - 1 + q;
            v[q] = ((unsigned)jj < 128u) ? row[jj] : 0.f;
        }
        #pragma unroll
        for (int p = 0; p < 4; p++) {
            acc[p] = fmaf(v[p + 0], w[kh * 3 + 0],
                     fmaf(v[p + 1], w[kh * 3 + 1],
                     fmaf(v[p + 2], w[kh * 3 + 2], acc[p])));
        }
    }
    float4* dst = reinterpret_cast<float4*>(g_zi + (size_t)n * HWSZ + i * WW + j0);
    *dst = make_float4(acc[0], acc[1], acc[2], acc[3]);
}

// One recurrent step, fully fused: ig (from zi) + hh-conv + LSTM + out-conv + logprob.
// 32x32 interior tile; h_new computed over 34x34 (1 halo) so out-conv stays in-kernel.
// Gate conv uses packed fma.rn.f32x2: 8 gates = 4 f32x2 pairs (i0i1,g0g1,f0f1,o0o1),
// matching the reference's split(gates,4) order along the last axis.
__global__ __launch_bounds__(256)
void k_step(const float* __restrict__ x,
            const float* __restrict__ Wih, const float* __restrict__ b_ih,
            const float* __restrict__ Whh, const float* __restrict__ b_hh,
            const float* __restrict__ Wout, const float* __restrict__ b_out,
            int t) {
    const int tid = threadIdx.x;
    const int tile = blockIdx.x;            // 0..15
    const int b = blockIdx.y;               // 0..31
    const int ti0 = (tile >> 2) * 32, tj0 = (tile & 3) * 32;
    const int rb = t & 1, wb = rb ^ 1;

    __shared__ float  s_zi[36 * 36];
    __shared__ float2 s_hp[36 * 36];
    __shared__ float2 s_hn[34 * 34];
    __shared__ __align__(16) float s_wih[72];
    __shared__ __align__(16) float s_whh[144];
    __shared__ __align__(16) float s_bg[8];
    __shared__ float s_wo[36], s_bo[2];
    __shared__ float s_red[8];

    // stage weights: Wih (3,3,1,8), Whh (3,3,2,8), Wout (3,3,4,2) -> take cin<2
    if (tid < 72)  s_wih[tid] = Wih[tid];
    if (tid < 144) s_whh[tid] = Whh[tid];
    if (tid < 36)  { int tap = tid >> 2, r = tid & 3; s_wo[tid] = Wout[tap * 8 + r]; }
    if (tid < 8)   s_bg[tid] = b_ih[tid] + b_hh[tid];
    if (tid < 2)   s_bo[tid] = b_out[tid];

    const float*  zib = g_zi + (size_t)(t * BB + b) * HWSZ;
    const float2* hpb = g_h[rb] + (size_t)b * HWSZ;
    #pragma unroll
    for (int q = 0; q < 6; q++) {
        int k = q * 256 + tid;
        if (k >= 36 * 36) break;
        int r = k / 36, c = k - r * 36;
        int gi = ti0 - 2 + r, gj = tj0 - 2 + c;
        bool in = ((unsigned)gi < 128u) & ((unsigned)gj < 128u);
        s_zi[k] = in ? zib[gi * WW + gj] : 0.f;
        s_hp[k] = in ? hpb[gi * WW + gj] : make_float2(0.f, 0.f);
    }
    __syncthreads();

    const float2* cpb = g_c[rb] + (size_t)b * HWSZ;
    float2* hnb = g_h[wb] + (size_t)b * HWSZ;
    float2* cnb = g_c[wb] + (size_t)b * HWSZ;

    const uint64_t* wih64 = reinterpret_cast<const uint64_t*>(s_wih);
    const uint64_t* whh64 = reinterpret_cast<const uint64_t*>(s_whh);
    const uint64_t* bg64  = reinterpret_cast<const uint64_t*>(s_bg);

    // 34x34 = 1156 gate points; 2 passes x 3 points/thread x 256 threads
    #pragma unroll
    for (int pass = 0; pass < 2; ++pass) {
        uint64_t gates2[3][4];
        int gi[3], gj[3];
        bool act[3], img[3];
        #pragma unroll
        for (int p = 0; p < 3; p++) {
            int idx = pass * 768 + p * 256 + tid;
            act[p] = idx < 1156;
            int a = act[p] ? idx : 0;
            gi[p] = a / 34;
            gj[p] = a - gi[p] * 34;
            int Gi = ti0 - 1 + gi[p], Gj = tj0 - 1 + gj[p];
            img[p] = act[p] && ((unsigned)Gi < 128u) && ((unsigned)Gj < 128u);
            #pragma unroll
            for (int q = 0; q < 4; q++) gates2[p][q] = bg64[q];
        }
        #pragma unroll
        for (int kh = 0; kh < 3; kh++) {
            #pragma unroll
            for (int kw = 0; kw < 3; kw++) {
                const int tap = kh * 3 + kw;
                uint64_t wi2[4], w02[4], w12[4];    // LDS.64 pair loads
                #pragma unroll
                for (int q = 0; q < 4; q++) {
                    wi2[q] = wih64[tap * 4 + q];
                    w02[q] = whh64[tap * 8 + q];
                    w12[q] = whh64[tap * 8 + 4 + q];
                }
                #pragma unroll
                for (int p = 0; p < 3; p++) {
                    if (!img[p]) continue;
                    int r = gi[p] + kh, c = gj[p] + kw;
                    float  zv = s_zi[r * 36 + c];
                    float2 hv = s_hp[r * 36 + c];
                    uint64_t z2 = pk2(zv, zv);
                    uint64_t hx2 = pk2(hv.x, hv.x);
                    uint64_t hy2 = pk2(hv.y, hv.y);
                    #pragma unroll
                    for (int q = 0; q < 4; q++) {
                        ffma2(gates2[p][q], z2,  wi2[q]);
                        ffma2(gates2[p][q], hx2, w02[q]);
                        ffma2(gates2[p][q], hy2, w12[q]);
                    }
                }
            }
        }
        #pragma unroll
        for (int p = 0; p < 3; p++) {
            if (!act[p]) continue;
            float2 hn = make_float2(0.f, 0.f);
            if (img[p]) {
                int Gi = ti0 - 1 + gi[p], Gj = tj0 - 1 + gj[p];
                float2 cp = cpb[Gi * WW + Gj];
                float gI0, gI1, gG0, gG1, gF0, gF1, gO0, gO1;
                upk2(gates2[p][0], gI0, gI1);
                upk2(gates2[p][1], gG0, gG1);
                upk2(gates2[p][2], gF0, gF1);
                upk2(gates2[p][3], gO0, gO1);
                float i0 = fsig(gI0), i1 = fsig(gI1);
                float t0 = ftanh(gG0), t1 = ftanh(gG1);
                float f0 = fsig(gF0 + 1.f), f1 = fsig(gF1 + 1.f);
                float o0 = fsig(gO0), o1 = fsig(gO1);
                float c0 = fmaf(f0, cp.x, i0 * t0);
                float c1 = fmaf(f1, cp.y, i1 * t1);
                hn.x = o0 * ftanh(c0);
                hn.y = o1 * ftanh(c1);
                bool inter = (gi[p] >= 1) & (gi[p] < 33) & (gj[p] >= 1) & (gj[p] < 33);
                if (inter) {
                    hnb[Gi * WW + Gj] = hn;
                    cnb[Gi * WW + Gj] = make_float2(c0, c1);
                }
            }
            s_hn[gi[p] * 34 + gj[p]] = hn;
        }
    }
    __syncthreads();

    // out-conv (2->2) over interior + log-prob for channel t+1
    const float* xb = x + (size_t)(b * CC + t + 1) * HWSZ;
    float acc = 0.f;
    #pragma unroll
    for (int q = 0; q < 4; q++) {
        int k = q * 256 + tid;
        int oi = k >> 5, oj = k & 31;
        float p0 = s_bo[0], p1 = s_bo[1];
        #pragma unroll
        for (int kh = 0; kh < 3; kh++) {
            #pragma unroll
            for (int kw = 0; kw < 3; kw++) {
                int tap = kh * 3 + kw;
                float2 hv = s_hn[(oi + kh) * 34 + oj + kw];
                p0 = fmaf(hv.x, s_wo[tap * 4 + 0], fmaf(hv.y, s_wo[tap * 4 + 2], p0));
                p1 = fmaf(hv.x, s_wo[tap * 4 + 1], fmaf(hv.y, s_wo[tap * 4 + 3], p1));
            }
        }
        float xv = xb[(ti0 + oi) * WW + tj0 + oj];
        float e = __expf(-p1);
        float z = (xv - p0) * e;
        acc = fmaf(-0.5f * z, z, acc) - p1 - 0.91893853320467274f;
    }
    #pragma unroll
    for (int off = 16; off; off >>= 1) acc += __shfl_down_sync(~0u, acc, off);
    if ((tid & 31) == 0) s_red[tid >> 5] = acc;
    __syncthreads();
    if (tid == 0) {
        float tot = 0.f;
        #pragma unroll
        for (int w = 0; w < 8; w++) tot += s_red[w];
        g_part[b * 16 + tile] += tot;   // exclusive owner per step: deterministic
    }
}

// final: channel-0 (bias-only) logprob + partial sum, one CTA per batch
__global__ void k_final(const float* __restrict__ x, const float* __restrict__ b_out,
                        float* __restrict__ out) {
    __shared__ float s_red[8];
    const int b = blockIdx.x;
    const float mu = b_out[0], ls = b_out[1];
    const float e = __expf(-ls);
    const float* xb = x + (size_t)b * CC * HWSZ;   // channel 0
    float acc = 0.f;
    for (int k = threadIdx.x; k < HWSZ; k += 256) {
        float z = (xb[k] - mu) * e;
        acc = fmaf(-0.5f * z, z, acc);
    }
    #pragma unroll
    for (int off = 16; off; off >>= 1) acc += __shfl_down_sync(~0u, acc, off);
    if ((threadIdx.x & 31) == 0) s_red[threadIdx.x >> 5] = acc;
    __syncthreads();
    if (threadIdx.x == 0) {
        float tot = 0.f;
        #pragma unroll
        for (int w = 0; w < 8; w++) tot += s_red[w];
        tot -= (float)HWSZ * (ls + 0.91893853320467274f);
        #pragma unroll
        for (int k = 0; k < 16; k++) tot += __ldg(&g_part[b * 16 + k]);
        out[b] = tot;
    }
}

// ---------------- launch ----------------
extern "C" void kernel_launch(void* const* d_in, const int* in_sizes, int n_in,
                              void* d_out, int out_size) {
    const float* x     = (const float*)d_in[0];
    const float* Win   = (const float*)d_in[1];
    const float* b_in  = (const float*)d_in[2];
    const float* Wih   = (const float*)d_in[3];
    const float* b_ih  = (const float*)d_in[4];
    const float* Whh   = (const float*)d_in[5];
    const float* b_hh  = (const float*)d_in[6];
    const float* Wout  = (const float*)d_in[7];
    const float* b_out = (const float*)d_in[8];
    (void)in_sizes; (void)n_in; (void)out_size;

    k_zi<<<(NT * BB * 128 * 32 + 255) / 256, 256>>>(x, Win, b_in);
    for (int t = 0; t < NT; t++)
        k_step<<<dim3(16, BB), 256>>>(x, Wih, b_ih, Whh, b_hh, Wout, b_out, t);
    k_final<<<BB, 256>>>(x, b_out, (float*)d_out);
}